// round 16
// baseline (speedup 1.0000x reference)
#include <cuda_runtime.h>
#include <cuda_bf16.h>
#include <cstdint>

// ---------------- problem constants ----------------
#define NNODES 100000
#define NEDGES 800000
#define NGRAPH 64
#define SCAN_CHUNK 1024
#define SCAN_NB ((NNODES + SCAN_CHUNK - 1) / SCAN_CHUNK)   // 98

// ---------------- scratch (static device globals; no allocation) ----------------
__device__ float4 g_bufA4[(size_t)NNODES * 32];   // 51.2 MB  (GEMM output, dinv-scaled fp32)
__device__ uint2  g_h1s[(size_t)NNODES * 64];     // 51.2 MB  (h1 pre-split bf16 hi/lo pairs)
__device__ float  g_dinv[NNODES];
__device__ int    g_cnti[NNODES];
__device__ int    g_off[NNODES + 1];
__device__ int    g_cursor[NNODES];
__device__ int    g_elist[NEDGES];
__device__ int    g_bsum[SCAN_NB];
__device__ int    g_bpre[SCAN_NB];
__device__ float  g_pool[NGRAPH * 128];
__device__ float  g_gcnt[NGRAPH];
// W fragments for mma.m16n8k16.bf16, pre-split hi/lo, fragment order (2 layers)
__device__ uint4  g_wfb[2][4096];   // 2 x 64 KB

// ---------------- bf16 split helpers ----------------
__device__ __forceinline__ void split2(float x, float y, uint32_t& hi, uint32_t& lo) {
    __nv_bfloat162 h = __floats2bfloat162_rn(x, y);
    float2 hf = __bfloat1622float2(h);
    __nv_bfloat162 l = __floats2bfloat162_rn(x - hf.x, y - hf.y);
    hi = *reinterpret_cast<uint32_t*>(&h);
    lo = *reinterpret_cast<uint32_t*>(&l);
}

#define MMA_BF16(d, a0, a1, a2, a3, b0, b1) \
    asm volatile("mma.sync.aligned.m16n8k16.row.col.f32.bf16.bf16.f32 " \
        "{%0,%1,%2,%3}, {%4,%5,%6,%7}, {%8,%9}, {%0,%1,%2,%3};" \
        : "+f"((d)[0]), "+f"((d)[1]), "+f"((d)[2]), "+f"((d)[3]) \
        : "r"(a0), "r"(a1), "r"(a2), "r"(a3), "r"(b0), "r"(b1))

// ---------------- W split-convert into fragment order ----------------
__global__ void wconv_kernel(const float* __restrict__ W, int sel) {
    int i = blockIdx.x * blockDim.x + threadIdx.x;
    if (i >= 4096) return;
    int lane = i & 31, ntg = (i >> 5) & 15, ks = i >> 9;
    int g = lane >> 2, t = lane & 3;
    int n = ntg * 8 + g;
    int k0 = ks * 16;
    float w0 = W[(size_t)(k0 + 2 * t)     * 128 + n];
    float w1 = W[(size_t)(k0 + 2 * t + 1) * 128 + n];
    float w2 = W[(size_t)(k0 + 2 * t + 8) * 128 + n];
    float w3 = W[(size_t)(k0 + 2 * t + 9) * 128 + n];
    uint32_t b0h, b0l, b1h, b1l;
    split2(w0, w1, b0h, b0l);
    split2(w2, w3, b1h, b1l);
    g_wfb[sel][i] = make_uint4(b0h, b1h, b0l, b1l);
}

#define LDA_P 68
#define GEMM_BM 32
#define GEMM_SMEM (GEMM_BM * LDA_P * 8)   // 17408 bytes

// ---------------- GEMM tile core: smA (split bf16) @ W[wsel] -> dinv-scaled fp32 ----------------
__device__ __forceinline__ void gemm_tile(const uint2* __restrict__ smA, int wsel,
                                          int block_row, int M) {
    const int tid = threadIdx.x, lane = tid & 31, wid = tid >> 5;
    const int wn = wid * 16;
    const int g  = lane >> 2;
    const int t  = lane & 3;
    const uint4* __restrict__ wf = g_wfb[wsel];

    float acc[2][2][4];
#pragma unroll
    for (int a = 0; a < 2; a++)
#pragma unroll
        for (int b = 0; b < 2; b++)
#pragma unroll
            for (int c = 0; c < 4; c++) acc[a][b][c] = 0.f;

#pragma unroll
    for (int ks = 0; ks < 8; ks++) {
        const int k0p = ks * 8;
        uint4 bf[2];
#pragma unroll
        for (int nt = 0; nt < 2; nt++)
            bf[nt] = wf[((size_t)(ks * 16 + wid * 2 + nt) << 5) + lane];

#pragma unroll
        for (int mt = 0; mt < 2; mt++) {
            const int r0 = (mt * 16 + g) * LDA_P;
            const int r8 = r0 + 8 * LDA_P;
            uint2 q0 = smA[r0 + k0p + t];
            uint2 q1 = smA[r8 + k0p + t];
            uint2 q2 = smA[r0 + k0p + t + 4];
            uint2 q3 = smA[r8 + k0p + t + 4];
#pragma unroll
            for (int nt = 0; nt < 2; nt++) {
                MMA_BF16(acc[mt][nt], q0.x, q1.x, q2.x, q3.x, bf[nt].x, bf[nt].y);
                MMA_BF16(acc[mt][nt], q0.x, q1.x, q2.x, q3.x, bf[nt].z, bf[nt].w);
                MMA_BF16(acc[mt][nt], q0.y, q1.y, q2.y, q3.y, bf[nt].x, bf[nt].y);
            }
        }
    }

    // epilogue with dinv row-scaling (fold of the GCN norm)
    float* C = reinterpret_cast<float*>(g_bufA4);
#pragma unroll
    for (int mt = 0; mt < 2; mt++) {
        const int row0 = block_row + mt * 16 + g;
        const float d0 = (row0 < M)     ? g_dinv[row0]     : 0.f;
        const float d8 = (row0 + 8 < M) ? g_dinv[row0 + 8] : 0.f;
#pragma unroll
        for (int nt = 0; nt < 2; nt++) {
            const int col = wn + nt * 8 + t * 2;
            if (row0 < M)
                *reinterpret_cast<float2*>(C + (size_t)row0 * 128 + col) =
                    make_float2(d0 * acc[mt][nt][0], d0 * acc[mt][nt][1]);
            if (row0 + 8 < M)
                *reinterpret_cast<float2*>(C + (size_t)(row0 + 8) * 128 + col) =
                    make_float2(d8 * acc[mt][nt][2], d8 * acc[mt][nt][3]);
        }
    }
}

// ---------------- GEMM1: bufA = dinv * (x @ W1)  (fp32 input, split on load) ----------------
__global__ __launch_bounds__(256, 4)
void tc_gemm1_kernel(const float* __restrict__ A, int wsel, int M) {
    extern __shared__ uint2 smA[];
    const int tid = threadIdx.x;
    const int block_row = blockIdx.x * GEMM_BM;

    for (int i = tid; i < GEMM_BM * 32; i += 256) {
        int r = i >> 5, c4 = (i & 31) * 4;
        float4 v = make_float4(0.f, 0.f, 0.f, 0.f);
        if (block_row + r < M)
            v = *reinterpret_cast<const float4*>(A + (size_t)(block_row + r) * 128 + c4);
        uint32_t h01, l01, h23, l23;
        split2(v.x, v.y, h01, l01);
        split2(v.z, v.w, h23, l23);
        int kp = (i & 31) * 2;
        smA[r * LDA_P + kp]     = make_uint2(h01, l01);
        smA[r * LDA_P + kp + 1] = make_uint2(h23, l23);
    }
    __syncthreads();
    gemm_tile(smA, wsel, block_row, M);
}

// ---------------- GEMM2: bufA = dinv * (h1 @ W2)  (pre-split uint2 input, pure copy) ----------------
__global__ __launch_bounds__(256, 4)
void tc_gemm2_kernel(int wsel, int M) {
    extern __shared__ uint2 smA[];
    const int tid = threadIdx.x;
    const int block_row = blockIdx.x * GEMM_BM;
    const uint4* __restrict__ src = reinterpret_cast<const uint4*>(g_h1s);  // 32 uint4/row

    for (int i = tid; i < GEMM_BM * 32; i += 256) {   // 1024 uint4, 4 per thread
        int r = i >> 5, q = i & 31;
        int kp = q * 2;
        uint4 v = make_uint4(0, 0, 0, 0);
        if (block_row + r < M)
            v = src[(size_t)(block_row + r) * 32 + q];
        smA[r * LDA_P + kp]     = make_uint2(v.x, v.y);
        smA[r * LDA_P + kp + 1] = make_uint2(v.z, v.w);
    }
    __syncthreads();
    gemm_tile(smA, wsel, block_row, M);
}

// ---------------- shared inner: pure gather-sum, then dinv[d]*sum + bias, relu ----------------
__device__ __forceinline__ float4 agg_row(int node, int lane, const float4* __restrict__ h4,
                                          const float* __restrict__ bias) {
    float4 acc = h4[(size_t)node * 32 + lane];   // self term (rows pre-scaled by dinv)

    const int beg = g_off[node];
    const int end = g_off[node + 1];
    int i = beg;
    for (; i + 7 < end; i += 8) {
        int s[8];
        float4 v[8];
#pragma unroll
        for (int u = 0; u < 8; u++) s[u] = g_elist[i + u];
#pragma unroll
        for (int u = 0; u < 8; u++) v[u] = h4[(size_t)s[u] * 32 + lane];
#pragma unroll
        for (int u = 0; u < 8; u++) {
            acc.x += v[u].x; acc.y += v[u].y; acc.z += v[u].z; acc.w += v[u].w;
        }
    }
    for (; i + 3 < end; i += 4) {
        int s[4];
        float4 v[4];
#pragma unroll
        for (int u = 0; u < 4; u++) s[u] = g_elist[i + u];
#pragma unroll
        for (int u = 0; u < 4; u++) v[u] = h4[(size_t)s[u] * 32 + lane];
#pragma unroll
        for (int u = 0; u < 4; u++) {
            acc.x += v[u].x; acc.y += v[u].y; acc.z += v[u].z; acc.w += v[u].w;
        }
    }
    for (; i < end; i++) {
        const float4 v = h4[(size_t)g_elist[i] * 32 + lane];
        acc.x += v.x; acc.y += v.y; acc.z += v.z; acc.w += v.w;
    }

    const float dd = g_dinv[node];
    const float4 bv = reinterpret_cast<const float4*>(bias)[lane];
    acc.x = fmaxf(fmaf(dd, acc.x, bv.x), 0.f);
    acc.y = fmaxf(fmaf(dd, acc.y, bv.y), 0.f);
    acc.z = fmaxf(fmaf(dd, acc.z, bv.z), 0.f);
    acc.w = fmaxf(fmaf(dd, acc.w, bv.w), 0.f);
    return acc;
}

// ---------------- layer-1 aggregation: writes h1 PRE-SPLIT (bf16 hi/lo) to g_h1s ----------------
__global__ __launch_bounds__(256, 4)
void agg_gather_kernel(const float* __restrict__ bias) {
    const int node = (blockIdx.x * blockDim.x + threadIdx.x) >> 5;
    const int lane = threadIdx.x & 31;
    if (node >= NNODES) return;
    float4 acc = agg_row(node, lane, g_bufA4, bias);
    uint32_t h01, l01, h23, l23;
    split2(acc.x, acc.y, h01, l01);
    split2(acc.z, acc.w, h23, l23);
    reinterpret_cast<uint4*>(g_h1s)[(size_t)node * 32 + lane] = make_uint4(h01, l01, h23, l23);
}

// ---------------- layer-2 aggregation FUSED with mean-pool accumulation ----------------
__global__ __launch_bounds__(256)
void agg_pool_kernel(const float* __restrict__ bias, const int* __restrict__ batch, int N) {
    __shared__ float sbuf[8][128];
    __shared__ int   sgid[8];
    const int tid  = threadIdx.x;
    const int wid  = tid >> 5;
    const int lane = tid & 31;
    const int node = blockIdx.x * 8 + wid;

    if (node < N) {
        float4 acc = agg_row(node, lane, g_bufA4, bias);
        *reinterpret_cast<float4*>(&sbuf[wid][lane * 4]) = acc;
        if (lane == 0) sgid[wid] = batch[node];
    } else if (lane == 0) {
        sgid[wid] = -1;
    }
    __syncthreads();

    if (tid < 128) {
        const int d = tid;
        int curg = -1;
        float run = 0.f;
#pragma unroll
        for (int w = 0; w < 8; w++) {
            const int g = sgid[w];
            if (g < 0) break;
            if (g != curg) {
                if (curg >= 0) atomicAdd(&g_pool[curg * 128 + d], run);
                curg = g; run = 0.f;
            }
            run += sbuf[w][d];
        }
        if (curg >= 0) atomicAdd(&g_pool[curg * 128 + d], run);
    }
}

// ================= CSR build =================
__global__ void zero_misc_kernel() {
    int i = blockIdx.x * blockDim.x + threadIdx.x;
    int stride = gridDim.x * blockDim.x;
    for (int k = i; k < NNODES; k += stride) g_cnti[k] = 0;
    if (i < NGRAPH * 128) g_pool[i] = 0.f;
}

__global__ void count_kernel(const int* __restrict__ dst, int E) {
    int e = blockIdx.x * blockDim.x + threadIdx.x;
    if (e >= E) return;
    atomicAdd(&g_cnti[dst[e]], 1);
}

// dinv from raw degrees (no scan dependency) — unblocks GEMM1 early
__global__ void dinv_kernel(int N) {
    int i = blockIdx.x * blockDim.x + threadIdx.x;
    if (i >= N) return;
    g_dinv[i] = rsqrtf((float)g_cnti[i] + 1.0f);
}

__global__ void gcnt_kernel(const int* __restrict__ batch, int N) {
    int g = threadIdx.x;
    if (g >= NGRAPH) return;
    int lo = 0, hi = N;
    while (lo < hi) { int m = (lo + hi) >> 1; if (batch[m] < g) lo = m + 1; else hi = m; }
    int b0 = lo;
    lo = 0; hi = N;
    while (lo < hi) { int m = (lo + hi) >> 1; if (batch[m] < g + 1) lo = m + 1; else hi = m; }
    g_gcnt[g] = (float)(lo - b0);
}

__global__ __launch_bounds__(256)
void scanA_kernel() {
    __shared__ int ssum[8];
    const int tid = threadIdx.x;
    const int base = blockIdx.x * SCAN_CHUNK + tid * 4;
    int s = 0;
#pragma unroll
    for (int j = 0; j < 4; j++) {
        int idx = base + j;
        if (idx < NNODES) s += g_cnti[idx];
    }
#pragma unroll
    for (int o = 16; o > 0; o >>= 1) s += __shfl_down_sync(0xffffffffu, s, o);
    if ((tid & 31) == 0) ssum[tid >> 5] = s;
    __syncthreads();
    if (tid == 0) {
        int tt = 0;
#pragma unroll
        for (int w = 0; w < 8; w++) tt += ssum[w];
        g_bsum[blockIdx.x] = tt;
    }
}

__global__ __launch_bounds__(128)
void scanB_kernel() {
    __shared__ int sh[128];
    const int t = threadIdx.x;
    int v = (t < SCAN_NB) ? g_bsum[t] : 0;
    sh[t] = v;
    __syncthreads();
    for (int o = 1; o < 128; o <<= 1) {
        int add = (t >= o) ? sh[t - o] : 0;
        __syncthreads();
        sh[t] += add;
        __syncthreads();
    }
    if (t < SCAN_NB) g_bpre[t] = sh[t] - v;
    if (t == SCAN_NB - 1) g_off[NNODES] = sh[t];
}

__global__ __launch_bounds__(256)
void scanC_kernel() {
    __shared__ int warpsum[8];
    const int tid = threadIdx.x;
    const int lane = tid & 31;
    const int warp = tid >> 5;
    const int base = blockIdx.x * SCAN_CHUNK + tid * 4;

    int v[4];
    int t = 0;
#pragma unroll
    for (int j = 0; j < 4; j++) {
        int idx = base + j;
        v[j] = (idx < NNODES) ? g_cnti[idx] : 0;
        t += v[j];
    }
    int incl = t;
#pragma unroll
    for (int o = 1; o < 32; o <<= 1) {
        int n = __shfl_up_sync(0xffffffffu, incl, o);
        if (lane >= o) incl += n;
    }
    if (lane == 31) warpsum[warp] = incl;
    __syncthreads();
    if (tid == 0) {
        int run = 0;
#pragma unroll
        for (int w = 0; w < 8; w++) { int x = warpsum[w]; warpsum[w] = run; run += x; }
    }
    __syncthreads();
    int run = g_bpre[blockIdx.x] + warpsum[warp] + (incl - t);
#pragma unroll
    for (int j = 0; j < 4; j++) {
        int idx = base + j;
        if (idx < NNODES) {
            g_off[idx] = run;
            g_cursor[idx] = run;
            run += v[j];
        }
    }
}

__global__ void fill_kernel(const int* __restrict__ src,
                            const int* __restrict__ dst, int E) {
    int e = blockIdx.x * blockDim.x + threadIdx.x;
    if (e >= E) return;
    int d = dst[e];
    int pos = atomicAdd(&g_cursor[d], 1);
    g_elist[pos] = src[e];
}

// ---------------- FC head ----------------
__global__ __launch_bounds__(128)
void fc_kernel(const float* __restrict__ W, const float* __restrict__ b,
               float* __restrict__ out) {
    __shared__ float row[128];
    const int g = blockIdx.x;
    const int j = threadIdx.x;
    const float inv = 1.0f / fmaxf(g_gcnt[g], 1.0f);
    row[j] = g_pool[g * 128 + j] * inv;
    __syncthreads();
    float acc = b[j];
#pragma unroll
    for (int k = 0; k < 128; k++)
        acc = fmaf(row[k], W[k * 128 + j], acc);
    out[g * 128 + j] = acc;
}

// ---------------- launch ----------------
extern "C" void kernel_launch(void* const* d_in, const int* in_sizes, int n_in,
                              void* d_out, int out_size) {
    const float* x   = (const float*)d_in[0];
    const int*   ei  = (const int*)d_in[1];    // int32 (JAX x64 disabled)
    const int*   bat = (const int*)d_in[2];
    const float* W1  = (const float*)d_in[3];
    const float* b1  = (const float*)d_in[4];
    const float* W2  = (const float*)d_in[5];
    const float* b2  = (const float*)d_in[6];
    const float* Wfc = (const float*)d_in[7];
    const float* bfc = (const float*)d_in[8];
    float*       out = (float*)d_out;

    const int N = in_sizes[2];
    const int E = in_sizes[1] / 2;
    const int* src = ei;
    const int* dst = ei + E;

    static cudaStream_t s_gemm = nullptr;
    static cudaEvent_t  ev_fork = nullptr, ev_dinv = nullptr, ev_g1 = nullptr;
    if (!s_gemm) {
        cudaStreamCreateWithFlags(&s_gemm, cudaStreamNonBlocking);
        cudaEventCreateWithFlags(&ev_fork, cudaEventDisableTiming);
        cudaEventCreateWithFlags(&ev_dinv, cudaEventDisableTiming);
        cudaEventCreateWithFlags(&ev_g1, cudaEventDisableTiming);
    }

    cudaFuncSetAttribute(tc_gemm1_kernel, cudaFuncAttributeMaxDynamicSharedMemorySize, GEMM_SMEM);
    cudaFuncSetAttribute(tc_gemm2_kernel, cudaFuncAttributeMaxDynamicSharedMemorySize, GEMM_SMEM);

    const int gemm_blocks = (N + GEMM_BM - 1) / GEMM_BM;   // 3125
    const int agg_blocks  = (N * 32 + 255) / 256;          // warp per node

    // --- fork: side stream does weight conversion + graph counts ---
    cudaEventRecord(ev_fork, 0);
    cudaStreamWaitEvent(s_gemm, ev_fork, 0);
    wconv_kernel<<<16, 256, 0, s_gemm>>>(W1, 0);
    wconv_kernel<<<16, 256, 0, s_gemm>>>(W2, 1);
    gcnt_kernel<<<1, NGRAPH, 0, s_gemm>>>(bat, N);

    // --- default stream: degrees -> dinv (GEMM1's only graph dependency) ---
    zero_misc_kernel<<<1184, 256>>>();
    count_kernel<<<(E + 255) / 256, 256>>>(dst, E);
    dinv_kernel<<<(N + 255) / 256, 256>>>(N);
    cudaEventRecord(ev_dinv, 0);

    // GEMM1 (side) overlaps with scans + fill (default)
    cudaStreamWaitEvent(s_gemm, ev_dinv, 0);
    tc_gemm1_kernel<<<gemm_blocks, 256, GEMM_SMEM, s_gemm>>>(x, 0, N);
    cudaEventRecord(ev_g1, s_gemm);

    scanA_kernel<<<SCAN_NB, 256>>>();
    scanB_kernel<<<1, 128>>>();
    scanC_kernel<<<SCAN_NB, 256>>>();
    fill_kernel<<<(E + 255) / 256, 256>>>(src, dst, E);

    // --- join, then the dependent chain ---
    cudaStreamWaitEvent(0, ev_g1, 0);
    agg_gather_kernel<<<agg_blocks, 256>>>(b1);               // writes pre-split h1
    tc_gemm2_kernel<<<gemm_blocks, 256, GEMM_SMEM>>>(1, N);   // pure-copy load phase
    agg_pool_kernel<<<(N + 7) / 8, 256>>>(b2, bat, N);
    fc_kernel<<<NGRAPH, 128>>>(Wfc, bfc, out);
}

// round 17
// speedup vs baseline: 1.0640x; 1.0640x over previous
#include <cuda_runtime.h>
#include <cuda_bf16.h>
#include <cstdint>

// ---------------- problem constants ----------------
#define NNODES 100000
#define NEDGES 800000
#define NGRAPH 64
#define SCAN_CHUNK 1024
#define SCAN_NB ((NNODES + SCAN_CHUNK - 1) / SCAN_CHUNK)   // 98

// ---------------- scratch (static device globals; no allocation) ----------------
__device__ float4 g_bufA4[(size_t)NNODES * 32];   // 51.2 MB  (GEMM output, dinv-scaled fp32)
__device__ uint2  g_h1s[(size_t)NNODES * 64];     // 51.2 MB  (h1 pre-split bf16 hi/lo pairs)
__device__ float  g_dinv[NNODES];
__device__ int    g_cnti[NNODES];
__device__ int    g_off[NNODES + 1];
__device__ int    g_cursor[NNODES];
__device__ int    g_elist[NEDGES];
__device__ int    g_bsum[SCAN_NB];
__device__ int    g_bpre[SCAN_NB];
__device__ float  g_pool[NGRAPH * 128];
__device__ float  g_gcnt[NGRAPH];
// W fragments for mma.m16n8k16.bf16, pre-split hi/lo, fragment order (2 layers)
__device__ uint4  g_wfb[2][4096];   // 2 x 64 KB

// ---------------- bf16 split helpers ----------------
__device__ __forceinline__ void split2(float x, float y, uint32_t& hi, uint32_t& lo) {
    __nv_bfloat162 h = __floats2bfloat162_rn(x, y);
    float2 hf = __bfloat1622float2(h);
    __nv_bfloat162 l = __floats2bfloat162_rn(x - hf.x, y - hf.y);
    hi = *reinterpret_cast<uint32_t*>(&h);
    lo = *reinterpret_cast<uint32_t*>(&l);
}

#define MMA_BF16(d, a0, a1, a2, a3, b0, b1) \
    asm volatile("mma.sync.aligned.m16n8k16.row.col.f32.bf16.bf16.f32 " \
        "{%0,%1,%2,%3}, {%4,%5,%6,%7}, {%8,%9}, {%0,%1,%2,%3};" \
        : "+f"((d)[0]), "+f"((d)[1]), "+f"((d)[2]), "+f"((d)[3]) \
        : "r"(a0), "r"(a1), "r"(a2), "r"(a3), "r"(b0), "r"(b1))

// ---------------- W split-convert into fragment order ----------------
__global__ void wconv_kernel(const float* __restrict__ W, int sel) {
    int i = blockIdx.x * blockDim.x + threadIdx.x;
    if (i >= 4096) return;
    int lane = i & 31, ntg = (i >> 5) & 15, ks = i >> 9;
    int g = lane >> 2, t = lane & 3;
    int n = ntg * 8 + g;
    int k0 = ks * 16;
    float w0 = W[(size_t)(k0 + 2 * t)     * 128 + n];
    float w1 = W[(size_t)(k0 + 2 * t + 1) * 128 + n];
    float w2 = W[(size_t)(k0 + 2 * t + 8) * 128 + n];
    float w3 = W[(size_t)(k0 + 2 * t + 9) * 128 + n];
    uint32_t b0h, b0l, b1h, b1l;
    split2(w0, w1, b0h, b0l);
    split2(w2, w3, b1h, b1l);
    g_wfb[sel][i] = make_uint4(b0h, b1h, b0l, b1l);
}

#define LDA_P 68
#define GEMM_BM 32
#define GEMM_SMEM (GEMM_BM * LDA_P * 8)   // 17408 bytes

// ---------------- GEMM tile core: smA (split bf16) @ W[wsel] -> dinv-scaled fp32 ----------------
__device__ __forceinline__ void gemm_tile(const uint2* __restrict__ smA, int wsel,
                                          int block_row, int M) {
    const int tid = threadIdx.x, lane = tid & 31, wid = tid >> 5;
    const int wn = wid * 16;
    const int g  = lane >> 2;
    const int t  = lane & 3;
    const uint4* __restrict__ wf = g_wfb[wsel];

    float acc[2][2][4];
#pragma unroll
    for (int a = 0; a < 2; a++)
#pragma unroll
        for (int b = 0; b < 2; b++)
#pragma unroll
            for (int c = 0; c < 4; c++) acc[a][b][c] = 0.f;

#pragma unroll
    for (int ks = 0; ks < 8; ks++) {
        const int k0p = ks * 8;
        uint4 bf[2];
#pragma unroll
        for (int nt = 0; nt < 2; nt++)
            bf[nt] = wf[((size_t)(ks * 16 + wid * 2 + nt) << 5) + lane];

#pragma unroll
        for (int mt = 0; mt < 2; mt++) {
            const int r0 = (mt * 16 + g) * LDA_P;
            const int r8 = r0 + 8 * LDA_P;
            uint2 q0 = smA[r0 + k0p + t];
            uint2 q1 = smA[r8 + k0p + t];
            uint2 q2 = smA[r0 + k0p + t + 4];
            uint2 q3 = smA[r8 + k0p + t + 4];
#pragma unroll
            for (int nt = 0; nt < 2; nt++) {
                MMA_BF16(acc[mt][nt], q0.x, q1.x, q2.x, q3.x, bf[nt].x, bf[nt].y);
                MMA_BF16(acc[mt][nt], q0.x, q1.x, q2.x, q3.x, bf[nt].z, bf[nt].w);
                MMA_BF16(acc[mt][nt], q0.y, q1.y, q2.y, q3.y, bf[nt].x, bf[nt].y);
            }
        }
    }

    // epilogue with dinv row-scaling (fold of the GCN norm)
    float* C = reinterpret_cast<float*>(g_bufA4);
#pragma unroll
    for (int mt = 0; mt < 2; mt++) {
        const int row0 = block_row + mt * 16 + g;
        const float d0 = (row0 < M)     ? g_dinv[row0]     : 0.f;
        const float d8 = (row0 + 8 < M) ? g_dinv[row0 + 8] : 0.f;
#pragma unroll
        for (int nt = 0; nt < 2; nt++) {
            const int col = wn + nt * 8 + t * 2;
            if (row0 < M)
                *reinterpret_cast<float2*>(C + (size_t)row0 * 128 + col) =
                    make_float2(d0 * acc[mt][nt][0], d0 * acc[mt][nt][1]);
            if (row0 + 8 < M)
                *reinterpret_cast<float2*>(C + (size_t)(row0 + 8) * 128 + col) =
                    make_float2(d8 * acc[mt][nt][2], d8 * acc[mt][nt][3]);
        }
    }
}

// ---------------- GEMM1: bufA = dinv * (x @ W1)  (fp32 input, split on load) ----------------
__global__ __launch_bounds__(256)
void tc_gemm1_kernel(const float* __restrict__ A, int wsel, int M) {
    extern __shared__ uint2 smA[];
    const int tid = threadIdx.x;
    const int block_row = blockIdx.x * GEMM_BM;

    for (int i = tid; i < GEMM_BM * 32; i += 256) {
        int r = i >> 5, c4 = (i & 31) * 4;
        float4 v = make_float4(0.f, 0.f, 0.f, 0.f);
        if (block_row + r < M)
            v = *reinterpret_cast<const float4*>(A + (size_t)(block_row + r) * 128 + c4);
        uint32_t h01, l01, h23, l23;
        split2(v.x, v.y, h01, l01);
        split2(v.z, v.w, h23, l23);
        int kp = (i & 31) * 2;
        smA[r * LDA_P + kp]     = make_uint2(h01, l01);
        smA[r * LDA_P + kp + 1] = make_uint2(h23, l23);
    }
    __syncthreads();
    gemm_tile(smA, wsel, block_row, M);
}

// ---------------- GEMM2: bufA = dinv * (h1 @ W2)  (pre-split uint2 input, pure copy) ----------------
__global__ __launch_bounds__(256)
void tc_gemm2_kernel(int wsel, int M) {
    extern __shared__ uint2 smA[];
    const int tid = threadIdx.x;
    const int block_row = blockIdx.x * GEMM_BM;
    const uint4* __restrict__ src = reinterpret_cast<const uint4*>(g_h1s);  // 32 uint4/row

    for (int i = tid; i < GEMM_BM * 32; i += 256) {   // 1024 uint4, 4 per thread
        int r = i >> 5, q = i & 31;
        int kp = q * 2;
        uint4 v = make_uint4(0, 0, 0, 0);
        if (block_row + r < M)
            v = src[(size_t)(block_row + r) * 32 + q];
        smA[r * LDA_P + kp]     = make_uint2(v.x, v.y);
        smA[r * LDA_P + kp + 1] = make_uint2(v.z, v.w);
    }
    __syncthreads();
    gemm_tile(smA, wsel, block_row, M);
}

// ---------------- shared inner: pure gather-sum, then dinv[d]*sum + bias, relu ----------------
__device__ __forceinline__ float4 agg_row(int node, int lane, const float4* __restrict__ h4,
                                          const float* __restrict__ bias) {
    float4 acc = h4[(size_t)node * 32 + lane];   // self term (rows pre-scaled by dinv)

    const int beg = g_off[node];
    const int end = g_off[node + 1];
    int i = beg;
    for (; i + 7 < end; i += 8) {
        int s[8];
        float4 v[8];
#pragma unroll
        for (int u = 0; u < 8; u++) s[u] = g_elist[i + u];
#pragma unroll
        for (int u = 0; u < 8; u++) v[u] = h4[(size_t)s[u] * 32 + lane];
#pragma unroll
        for (int u = 0; u < 8; u++) {
            acc.x += v[u].x; acc.y += v[u].y; acc.z += v[u].z; acc.w += v[u].w;
        }
    }
    for (; i + 3 < end; i += 4) {
        int s[4];
        float4 v[4];
#pragma unroll
        for (int u = 0; u < 4; u++) s[u] = g_elist[i + u];
#pragma unroll
        for (int u = 0; u < 4; u++) v[u] = h4[(size_t)s[u] * 32 + lane];
#pragma unroll
        for (int u = 0; u < 4; u++) {
            acc.x += v[u].x; acc.y += v[u].y; acc.z += v[u].z; acc.w += v[u].w;
        }
    }
    for (; i < end; i++) {
        const float4 v = h4[(size_t)g_elist[i] * 32 + lane];
        acc.x += v.x; acc.y += v.y; acc.z += v.z; acc.w += v.w;
    }

    const float dd = g_dinv[node];
    const float4 bv = reinterpret_cast<const float4*>(bias)[lane];
    acc.x = fmaxf(fmaf(dd, acc.x, bv.x), 0.f);
    acc.y = fmaxf(fmaf(dd, acc.y, bv.y), 0.f);
    acc.z = fmaxf(fmaf(dd, acc.z, bv.z), 0.f);
    acc.w = fmaxf(fmaf(dd, acc.w, bv.w), 0.f);
    return acc;
}

// ---------------- layer-1 aggregation: writes h1 PRE-SPLIT (bf16 hi/lo) to g_h1s ----------------
__global__ __launch_bounds__(256)
void agg_gather_kernel(const float* __restrict__ bias) {
    const int node = (blockIdx.x * blockDim.x + threadIdx.x) >> 5;
    const int lane = threadIdx.x & 31;
    if (node >= NNODES) return;
    float4 acc = agg_row(node, lane, g_bufA4, bias);
    uint32_t h01, l01, h23, l23;
    split2(acc.x, acc.y, h01, l01);
    split2(acc.z, acc.w, h23, l23);
    reinterpret_cast<uint4*>(g_h1s)[(size_t)node * 32 + lane] = make_uint4(h01, l01, h23, l23);
}

// ---------------- layer-2 aggregation FUSED with mean-pool accumulation ----------------
__global__ __launch_bounds__(256)
void agg_pool_kernel(const float* __restrict__ bias, const int* __restrict__ batch, int N) {
    __shared__ float sbuf[8][128];
    __shared__ int   sgid[8];
    const int tid  = threadIdx.x;
    const int wid  = tid >> 5;
    const int lane = tid & 31;
    const int node = blockIdx.x * 8 + wid;

    if (node < N) {
        float4 acc = agg_row(node, lane, g_bufA4, bias);
        *reinterpret_cast<float4*>(&sbuf[wid][lane * 4]) = acc;
        if (lane == 0) sgid[wid] = batch[node];
    } else if (lane == 0) {
        sgid[wid] = -1;
    }
    __syncthreads();

    if (tid < 128) {
        const int d = tid;
        int curg = -1;
        float run = 0.f;
#pragma unroll
        for (int w = 0; w < 8; w++) {
            const int g = sgid[w];
            if (g < 0) break;
            if (g != curg) {
                if (curg >= 0) atomicAdd(&g_pool[curg * 128 + d], run);
                curg = g; run = 0.f;
            }
            run += sbuf[w][d];
        }
        if (curg >= 0) atomicAdd(&g_pool[curg * 128 + d], run);
    }
}

// ================= CSR build =================
__global__ void count_kernel(const int* __restrict__ dst, int E) {
    int e = blockIdx.x * blockDim.x + threadIdx.x;
    if (e >= E) return;
    atomicAdd(&g_cnti[dst[e]], 1);
}

// dinv from raw degrees (no scan dependency) — unblocks GEMM1 early
__global__ void dinv_kernel(int N) {
    int i = blockIdx.x * blockDim.x + threadIdx.x;
    if (i >= N) return;
    g_dinv[i] = rsqrtf((float)g_cnti[i] + 1.0f);
}

__global__ void gcnt_kernel(const int* __restrict__ batch, int N) {
    int g = threadIdx.x;
    if (g >= NGRAPH) return;
    int lo = 0, hi = N;
    while (lo < hi) { int m = (lo + hi) >> 1; if (batch[m] < g) lo = m + 1; else hi = m; }
    int b0 = lo;
    lo = 0; hi = N;
    while (lo < hi) { int m = (lo + hi) >> 1; if (batch[m] < g + 1) lo = m + 1; else hi = m; }
    g_gcnt[g] = (float)(lo - b0);
}

__global__ __launch_bounds__(256)
void scanA_kernel() {
    __shared__ int ssum[8];
    const int tid = threadIdx.x;
    const int base = blockIdx.x * SCAN_CHUNK + tid * 4;
    int s = 0;
#pragma unroll
    for (int j = 0; j < 4; j++) {
        int idx = base + j;
        if (idx < NNODES) s += g_cnti[idx];
    }
#pragma unroll
    for (int o = 16; o > 0; o >>= 1) s += __shfl_down_sync(0xffffffffu, s, o);
    if ((tid & 31) == 0) ssum[tid >> 5] = s;
    __syncthreads();
    if (tid == 0) {
        int tt = 0;
#pragma unroll
        for (int w = 0; w < 8; w++) tt += ssum[w];
        g_bsum[blockIdx.x] = tt;
    }
}

__global__ __launch_bounds__(128)
void scanB_kernel() {
    __shared__ int sh[128];
    const int t = threadIdx.x;
    int v = (t < SCAN_NB) ? g_bsum[t] : 0;
    sh[t] = v;
    __syncthreads();
    for (int o = 1; o < 128; o <<= 1) {
        int add = (t >= o) ? sh[t - o] : 0;
        __syncthreads();
        sh[t] += add;
        __syncthreads();
    }
    if (t < SCAN_NB) g_bpre[t] = sh[t] - v;
    if (t == SCAN_NB - 1) g_off[NNODES] = sh[t];
}

__global__ __launch_bounds__(256)
void scanC_kernel() {
    __shared__ int warpsum[8];
    const int tid = threadIdx.x;
    const int lane = tid & 31;
    const int warp = tid >> 5;
    const int base = blockIdx.x * SCAN_CHUNK + tid * 4;

    int v[4];
    int t = 0;
#pragma unroll
    for (int j = 0; j < 4; j++) {
        int idx = base + j;
        v[j] = (idx < NNODES) ? g_cnti[idx] : 0;
        t += v[j];
    }
    int incl = t;
#pragma unroll
    for (int o = 1; o < 32; o <<= 1) {
        int n = __shfl_up_sync(0xffffffffu, incl, o);
        if (lane >= o) incl += n;
    }
    if (lane == 31) warpsum[warp] = incl;
    __syncthreads();
    if (tid == 0) {
        int run = 0;
#pragma unroll
        for (int w = 0; w < 8; w++) { int x = warpsum[w]; warpsum[w] = run; run += x; }
    }
    __syncthreads();
    int run = g_bpre[blockIdx.x] + warpsum[warp] + (incl - t);
#pragma unroll
    for (int j = 0; j < 4; j++) {
        int idx = base + j;
        if (idx < NNODES) {
            g_off[idx] = run;
            g_cursor[idx] = run;
            run += v[j];
        }
    }
}

__global__ void fill_kernel(const int* __restrict__ src,
                            const int* __restrict__ dst, int E) {
    int e = blockIdx.x * blockDim.x + threadIdx.x;
    if (e >= E) return;
    int d = dst[e];
    int pos = atomicAdd(&g_cursor[d], 1);
    g_elist[pos] = src[e];
}

// ---------------- FC head ----------------
__global__ __launch_bounds__(128)
void fc_kernel(const float* __restrict__ W, const float* __restrict__ b,
               float* __restrict__ out) {
    __shared__ float row[128];
    const int g = blockIdx.x;
    const int j = threadIdx.x;
    const float inv = 1.0f / fmaxf(g_gcnt[g], 1.0f);
    row[j] = g_pool[g * 128 + j] * inv;
    __syncthreads();
    float acc = b[j];
#pragma unroll
    for (int k = 0; k < 128; k++)
        acc = fmaf(row[k], W[k * 128 + j], acc);
    out[g * 128 + j] = acc;
}

// ---------------- launch ----------------
extern "C" void kernel_launch(void* const* d_in, const int* in_sizes, int n_in,
                              void* d_out, int out_size) {
    const float* x   = (const float*)d_in[0];
    const int*   ei  = (const int*)d_in[1];    // int32 (JAX x64 disabled)
    const int*   bat = (const int*)d_in[2];
    const float* W1  = (const float*)d_in[3];
    const float* b1  = (const float*)d_in[4];
    const float* W2  = (const float*)d_in[5];
    const float* b2  = (const float*)d_in[6];
    const float* Wfc = (const float*)d_in[7];
    const float* bfc = (const float*)d_in[8];
    float*       out = (float*)d_out;

    const int N = in_sizes[2];
    const int E = in_sizes[1] / 2;
    const int* src = ei;
    const int* dst = ei + E;

    static cudaStream_t s_gemm = nullptr;
    static cudaEvent_t  ev_fork = nullptr, ev_dinv = nullptr, ev_g1 = nullptr;
    static void* p_cnti = nullptr;
    static void* p_pool = nullptr;
    if (!s_gemm) {
        cudaStreamCreateWithFlags(&s_gemm, cudaStreamNonBlocking);
        cudaEventCreateWithFlags(&ev_fork, cudaEventDisableTiming);
        cudaEventCreateWithFlags(&ev_dinv, cudaEventDisableTiming);
        cudaEventCreateWithFlags(&ev_g1, cudaEventDisableTiming);
        cudaGetSymbolAddress(&p_cnti, g_cnti);
        cudaGetSymbolAddress(&p_pool, g_pool);
    }

    cudaFuncSetAttribute(tc_gemm1_kernel, cudaFuncAttributeMaxDynamicSharedMemorySize, GEMM_SMEM);
    cudaFuncSetAttribute(tc_gemm2_kernel, cudaFuncAttributeMaxDynamicSharedMemorySize, GEMM_SMEM);

    const int gemm_blocks = (N + GEMM_BM - 1) / GEMM_BM;   // 3125
    const int agg_blocks  = (N * 32 + 255) / 256;          // warp per node

    // --- fork: side stream does weight conversion + graph counts + pool zero ---
    cudaEventRecord(ev_fork, 0);
    cudaStreamWaitEvent(s_gemm, ev_fork, 0);
    cudaMemsetAsync(p_pool, 0, NGRAPH * 128 * sizeof(float), s_gemm);
    wconv_kernel<<<16, 256, 0, s_gemm>>>(W1, 0);
    wconv_kernel<<<16, 256, 0, s_gemm>>>(W2, 1);
    gcnt_kernel<<<1, NGRAPH, 0, s_gemm>>>(bat, N);

    // --- default stream: degrees -> dinv (GEMM1's only graph dependency) ---
    cudaMemsetAsync(p_cnti, 0, NNODES * sizeof(int), 0);
    count_kernel<<<(E + 255) / 256, 256>>>(dst, E);
    dinv_kernel<<<(N + 255) / 256, 256>>>(N);
    cudaEventRecord(ev_dinv, 0);

    // GEMM1 (side) overlaps with scans + fill (default)
    cudaStreamWaitEvent(s_gemm, ev_dinv, 0);
    tc_gemm1_kernel<<<gemm_blocks, 256, GEMM_SMEM, s_gemm>>>(x, 0, N);
    cudaEventRecord(ev_g1, s_gemm);

    scanA_kernel<<<SCAN_NB, 256>>>();
    scanB_kernel<<<1, 128>>>();
    scanC_kernel<<<SCAN_NB, 256>>>();
    fill_kernel<<<(E + 255) / 256, 256>>>(src, dst, E);

    // --- join, then the dependent chain ---
    cudaStreamWaitEvent(0, ev_g1, 0);
    agg_gather_kernel<<<agg_blocks, 256>>>(b1);               // writes pre-split h1
    tc_gemm2_kernel<<<gemm_blocks, 256, GEMM_SMEM>>>(1, N);   // pure-copy load phase
    agg_pool_kernel<<<(N + 7) / 8, 256>>>(b2, bat, N);
    fc_kernel<<<NGRAPH, 128>>>(Wfc, bfc, out);
}